// round 8
// baseline (speedup 1.0000x reference)
#include <cuda_runtime.h>

#define Bn 8
#define Cn 24
#define Mn 960
#define Wn 15                   // 64-bit words per row (960/64)
#define ROWS (Bn*Mn)            // 7680
#define NW (ROWS*Wn)            // 115200 words

typedef unsigned long long u64;

// Global bitmap planes: frontier (r=0) + 6 hrode planes r = 4,6,7,8,9,10.
__device__ u64 g_F[NW];
__device__ u64 g_P[6][NW];
// plane aliases: g_P[5]=r10, g_P[4]=r9, g_P[3]=r8, g_P[2]=r7, g_P[1]=r6, g_P[0]=r4

// ── K1: pack + horizontal erosion (row-local, no halo, DRAM-streaming).
#define PR 16                   // rows per block
__global__ void __launch_bounds__(256) pack_kernel(const float* __restrict__ in) {
    __shared__ u64 sF[PR][Wn];
    const int lane = threadIdx.x & 31;
    const int warp = threadIdx.x >> 5;
    const int row0 = blockIdx.x * PR;                 // global row = b*Mn + y

#pragma unroll
    for (int i = 0; i < PR / 8; i++) {                // 8 warps, 2 rows each
        int rr = warp + (i << 3);
        int row = row0 + rr;
        int b = row / Mn, y = row - b * Mn;
        const float* p = in + ((size_t)(b * Cn + 1) * Mn + y) * Mn + lane;
        float v[30];
#pragma unroll
        for (int j = 0; j < 30; j++) v[j] = p[j * 32];
        unsigned bb[30];
#pragma unroll
        for (int j = 0; j < 30; j++) bb[j] = __ballot_sync(0xffffffffu, v[j] == 0.0f);
        if (lane < Wn) {
            unsigned lo = 0, hi = 0;
#pragma unroll
            for (int k = 0; k < Wn; k++)
                if (lane == k) { lo = bb[2 * k]; hi = bb[2 * k + 1]; }
            sF[rr][lane] = ((u64)hi << 32) | lo;
        }
    }
    __syncthreads();

    int t = threadIdx.x;
    if (t < PR * Wn) {                                // 240 words
        int rr = t / Wn, w = t - rr * Wn;
        u64 c = sF[rr][w];
        u64 l = (w > 0)      ? sF[rr][w - 1] : 0ULL;
        u64 r = (w < Wn - 1) ? sF[rr][w + 1] : 0ULL;
        int i = (row0 + rr) * Wn + w;
        g_F[i] = c;
        u64 acc = c;
#pragma unroll
        for (int d = 1; d <= 10; d++) {
            acc &= ((c << d) | (l >> (64 - d))) & ((c >> d) | (r << (64 - d)));
            if (d == 4)       g_P[0][i] = acc;
            else if (d == 6)  g_P[1][i] = acc;
            else if (d == 7)  g_P[2][i] = acc;
            else if (d == 8)  g_P[3][i] = acc;
            else if (d == 9)  g_P[4][i] = acc;
            else if (d == 10) g_P[5][i] = acc;
        }
    }
}

// ── K2: warp-autonomous morph. Warp owns 2 output rows; no smem, no barriers.
// Half-warp 0 (lanes 0-15): eroded pair (y0-1, y0); half 1: pair (y0+1, y0+2).
// 34 subsumption-shared loads per lane; border via shuffles; coalesced expand.
__global__ void __launch_bounds__(128, 8) morph_kernel(float* __restrict__ out) {
    const unsigned FULL = 0xffffffffu;
    const int lane = threadIdx.x & 31;
    const int wid  = threadIdx.x >> 5;
    const int yo   = (blockIdx.x * 4 + wid) * 2;      // global output row base
    const int b    = yo / Mn;
    const int y0   = yo - b * Mn;                     // image-local
    const int half = lane >> 4;
    const int wl   = lane & 15;
    const int w    = wl < 14 ? wl : 14;               // lanes 15/31 duplicate w=14

    const int yA = y0 - 1 + half * 2;                 // pair rows yA, yA+1
    auto idx = [&](int yy) {
        yy = yy < 0 ? 0 : (yy > Mn - 1 ? Mn - 1 : yy);
        return (b * Mn + yy) * Wn + w;
    };

    // shared terms (20 loads, harmless-superset trick)
    u64 s = g_P[4][idx(yA-3)] & g_P[4][idx(yA-2)] & g_P[4][idx(yA-1)] & g_P[4][idx(yA)]
          & g_P[4][idx(yA+1)] & g_P[4][idx(yA+2)] & g_P[4][idx(yA+3)] & g_P[4][idx(yA+4)];
    s &= g_P[3][idx(yA-5)] & g_P[3][idx(yA-4)] & g_P[3][idx(yA+5)] & g_P[3][idx(yA+6)];
    s &= g_P[2][idx(yA-6)] & g_P[2][idx(yA+7)];
    s &= g_P[1][idx(yA-7)] & g_P[1][idx(yA+8)];
    s &= g_P[0][idx(yA-8)] & g_P[0][idx(yA+9)];
    s &= g_F[idx(yA-9)]    & g_F[idx(yA+10)];
    // per-row extras (7 + 7 loads)
    u64 ea = s & g_P[5][idx(yA)]   & g_P[4][idx(yA-4)] & g_P[3][idx(yA-6)]
               & g_P[2][idx(yA-7)] & g_P[1][idx(yA-8)] & g_P[0][idx(yA-9)]
               & g_F[idx(yA-10)];
    u64 eb = s & g_P[5][idx(yA+1)] & g_P[4][idx(yA+5)] & g_P[3][idx(yA+7)]
               & g_P[2][idx(yA+8)] & g_P[1][idx(yA+9)] & g_P[0][idx(yA+10)]
               & g_F[idx(yA+11)];
    ea = (yA     >= 10 && yA     <= Mn - 11) ? ea : 0ULL;
    eb = (yA + 1 >= 10 && yA + 1 <= Mn - 11) ? eb : 0ULL;

    // exchange with the other half-warp (same word, other row pair)
    u64 a_other = __shfl_xor_sync(FULL, ea, 16);
    u64 b_other = __shfl_xor_sync(FULL, eb, 16);

    // this lane's border row: half0 -> y0 (e=eb), half1 -> y0+1 (e=ea)
    u64 e  = half ? ea : eb;
    u64 up = half ? b_other : ea;        // e(y-1)
    u64 dn = half ? eb : a_other;        // e(y+1)
    u64 lft = __shfl_up_sync(FULL, e, 1);
    u64 rgt = __shfl_down_sync(FULL, e, 1);
    if (wl == 0)  lft = 0ULL;
    if (wl >= 14) rgt = 0ULL;
    u64 border = (e | up | dn | (e << 1) | (lft >> 63) | (e >> 1) | (rgt << 63)) & ~e;

    // expand: 2 rows x 240 float4 = 480 chunks, 15 per lane, coalesced stores
    float4* o = (float4*)out + (size_t)yo * (Mn / 4);
#pragma unroll
    for (int k = 0; k < 15; k++) {
        int c  = (k << 5) + lane;                     // 0..479
        int rr = c >= 240;
        int cc = c - rr * 240;
        int src = (rr << 4) + (cc >> 4);
        u64 bw = __shfl_sync(FULL, border, src);
        unsigned nib = (unsigned)(bw >> ((cc & 15) << 2)) & 15u;
        o[(size_t)rr * 240 + cc] =
            make_float4(nib & 1u ? 1.0f : 0.0f, nib & 2u ? 1.0f : 0.0f,
                        nib & 4u ? 1.0f : 0.0f, nib & 8u ? 1.0f : 0.0f);
    }
}

extern "C" void kernel_launch(void* const* d_in, const int* in_sizes, int n_in,
                              void* d_out, int out_size) {
    const float* map_features = (const float*)d_in[0];
    float* out = (float*)d_out;
    pack_kernel<<<ROWS / PR, 256>>>(map_features);    // 480 blocks
    morph_kernel<<<ROWS / 8, 128>>>(out);             // 960 blocks, 4 warps each
}

// round 9
// speedup vs baseline: 1.0151x; 1.0151x over previous
#include <cuda_runtime.h>

#define Bn 8
#define Cn 24
#define Mn 960
#define Wn 15                   // real 64-bit words per row (960/64)
#define WS 16                   // padded words per row (16B vector alignment)
#define ROWS (Bn*Mn)            // 7680

typedef unsigned long long u64;

// Global bitmap planes, padded to 16 words/row, stored as 16B vectors.
// plane order: g_P2[5]=r10, [4]=r9, [3]=r8, [2]=r7, [1]=r6, [0]=r4
__device__ ulonglong2 g_F2[ROWS * 8];
__device__ ulonglong2 g_P2[6][ROWS * 8];

static __device__ __forceinline__ ulonglong2 and2(ulonglong2 a, ulonglong2 b) {
    return make_ulonglong2(a.x & b.x, a.y & b.y);
}

// ── K1: pack + horizontal erosion (row-local, no halo, DRAM-streaming).
#define PR 16                   // rows per block
__global__ void __launch_bounds__(256) pack_kernel(const float* __restrict__ in) {
    __shared__ u64 sF[PR][Wn];
    const int lane = threadIdx.x & 31;
    const int warp = threadIdx.x >> 5;
    const int row0 = blockIdx.x * PR;                 // global row = b*Mn + y

#pragma unroll
    for (int i = 0; i < PR / 8; i++) {                // 8 warps, 2 rows each
        int rr = warp + (i << 3);
        int row = row0 + rr;
        int b = row / Mn, y = row - b * Mn;
        const float* p = in + ((size_t)(b * Cn + 1) * Mn + y) * Mn + lane;
        float v[30];
#pragma unroll
        for (int j = 0; j < 30; j++) v[j] = p[j * 32];
        unsigned bb[30];
#pragma unroll
        for (int j = 0; j < 30; j++) bb[j] = __ballot_sync(0xffffffffu, v[j] == 0.0f);
        if (lane < Wn) {
            unsigned lo = 0, hi = 0;
#pragma unroll
            for (int k = 0; k < Wn; k++)
                if (lane == k) { lo = bb[2 * k]; hi = bb[2 * k + 1]; }
            sF[rr][lane] = ((u64)hi << 32) | lo;
        }
    }
    __syncthreads();

    // 256 tasks exactly: PR rows x 16 words (word 15 = zero pad)
    int t = threadIdx.x;
    int rr = t >> 4, w = t & 15;
    int i = (row0 + rr) * WS + w;
    u64* Fw = (u64*)g_F2;
    if (w == Wn) {                                    // zero the pad word
        Fw[i] = 0ULL;
#pragma unroll
        for (int p = 0; p < 6; p++) ((u64*)g_P2[p])[i] = 0ULL;
    } else {
        u64 c = sF[rr][w];
        u64 l = (w > 0)      ? sF[rr][w - 1] : 0ULL;
        u64 r = (w < Wn - 1) ? sF[rr][w + 1] : 0ULL;
        Fw[i] = c;
        u64 acc = c;
#pragma unroll
        for (int d = 1; d <= 10; d++) {
            acc &= ((c << d) | (l >> (64 - d))) & ((c >> d) | (r << (64 - d)));
            if (d == 4)       ((u64*)g_P2[0])[i] = acc;
            else if (d == 6)  ((u64*)g_P2[1])[i] = acc;
            else if (d == 7)  ((u64*)g_P2[2])[i] = acc;
            else if (d == 8)  ((u64*)g_P2[3])[i] = acc;
            else if (d == 9)  ((u64*)g_P2[4])[i] = acc;
            else if (d == 10) ((u64*)g_P2[5])[i] = acc;
        }
    }
}

// ── K2: vertical 21-term AND with 128-bit loads (2 words per thread-task),
// then cross-border + float4 expand.
#define RB 16                   // output rows per block; grid = 480
__global__ void __launch_bounds__(256, 4) morph_kernel(float* __restrict__ out) {
    __shared__ u64 sE[RB + 2][WS];                    // padded; word 15 is 0
    __shared__ u64 sB[RB][WS];
    const int t  = threadIdx.x;
    const int r0 = blockIdx.x * RB;
    const int b  = r0 / Mn;
    const int y0 = r0 - b * Mn;

    // Phase B: eroded rows y0-1 .. y0+RB, 18 rows x 8 vector-words = 144 tasks.
    if (t < (RB + 2) * 8) {
        int rr = t >> 3, w4 = t & 7;
        int y = y0 + rr - 1;
        ulonglong2 e = make_ulonglong2(0ULL, 0ULL);
        if (y >= 10 && y <= Mn - 11) {
            size_t j = (size_t)(b * Mn + y) * 8 + w4;  // vector index, row stride 8
            ulonglong2 v0  = g_P2[5][j];
            ulonglong2 v1  = g_P2[4][j - 8];   ulonglong2 v2  = g_P2[4][j + 8];
            ulonglong2 v3  = g_P2[4][j - 16];  ulonglong2 v4  = g_P2[4][j + 16];
            ulonglong2 v5  = g_P2[4][j - 24];  ulonglong2 v6  = g_P2[4][j + 24];
            ulonglong2 v7  = g_P2[4][j - 32];  ulonglong2 v8  = g_P2[4][j + 32];
            ulonglong2 v9  = g_P2[3][j - 40];  ulonglong2 v10 = g_P2[3][j + 40];
            ulonglong2 v11 = g_P2[3][j - 48];  ulonglong2 v12 = g_P2[3][j + 48];
            ulonglong2 v13 = g_P2[2][j - 56];  ulonglong2 v14 = g_P2[2][j + 56];
            ulonglong2 v15 = g_P2[1][j - 64];  ulonglong2 v16 = g_P2[1][j + 64];
            ulonglong2 v17 = g_P2[0][j - 72];  ulonglong2 v18 = g_P2[0][j + 72];
            ulonglong2 v19 = g_F2[j - 80];     ulonglong2 v20 = g_F2[j + 80];
            ulonglong2 a0 = and2(and2(v0, v1),  and2(v2, v3));
            ulonglong2 a1 = and2(and2(v4, v5),  and2(v6, v7));
            ulonglong2 a2 = and2(and2(v8, v9),  and2(v10, v11));
            ulonglong2 a3 = and2(and2(v12, v13), and2(v14, v15));
            ulonglong2 a4 = and2(and2(v16, v17), and2(v18, v19));
            e = and2(and2(and2(a0, a1), and2(a2, a3)), and2(a4, v20));
        }
        sE[rr][2 * w4]     = e.x;
        sE[rr][2 * w4 + 1] = e.y;
    }
    __syncthreads();

    // Phase C: border = dilate(e, cross) & ~e, 240 tasks (1/thread).
    if (t < RB * Wn) {
        int rr = t / Wn, w = t - rr * Wn;
        u64 e  = sE[rr + 1][w];
        u64 eu = sE[rr][w];
        u64 ed = sE[rr + 2][w];
        u64 l  = (w > 0) ? sE[rr + 1][w - 1] : 0ULL;
        u64 r  = sE[rr + 1][w + 1];                   // pad word is 0 at w=14
        u64 d = e | eu | ed | (e << 1) | (l >> 63) | (e >> 1) | (r << 63);
        sB[rr][w] = d & ~e;
    }
    __syncthreads();

    // Phase D: bits -> float4, coalesced stores (3840 chunks, 15/thread exact).
    float4* o = (float4*)out + (size_t)r0 * (Mn / 4);
#pragma unroll
    for (int k = 0; k < (RB * (Mn / 4)) / 256; k++) {
        int c = t + (k << 8);
        int rr = c / (Mn / 4), cc = c - rr * (Mn / 4);
        u64 bw = sB[rr][cc >> 4];
        unsigned nib = (unsigned)(bw >> ((cc & 15) << 2)) & 15u;
        o[c] = make_float4(nib & 1u ? 1.0f : 0.0f, nib & 2u ? 1.0f : 0.0f,
                           nib & 4u ? 1.0f : 0.0f, nib & 8u ? 1.0f : 0.0f);
    }
}

extern "C" void kernel_launch(void* const* d_in, const int* in_sizes, int n_in,
                              void* d_out, int out_size) {
    const float* map_features = (const float*)d_in[0];
    float* out = (float*)d_out;
    pack_kernel<<<ROWS / PR, 256>>>(map_features);    // 480 blocks
    morph_kernel<<<ROWS / RB, 256>>>(out);            // 480 blocks
}